// round 3
// baseline (speedup 1.0000x reference)
#include <cuda_runtime.h>
#include <cuda_bf16.h>
#include <math.h>

#define HW     9216    // 96*96
#define DIM    96
#define NSAMP  8
#define NBLK16 16      // sample * direction
#define NSLICE 9       // 9216 / 1024 pixel slices per (sample,dir)
#define NCTA   (NBLK16 * NSLICE)   // 144 CTAs = single wave
#define TPB    1024
#define INFG   20000   // > 96; (INFG+96)^2 ~ 4.04e8 fits int32

__device__ int g_max16[NBLK16] = { -1,-1,-1,-1,-1,-1,-1,-1,
                                   -1,-1,-1,-1,-1,-1,-1,-1 };
__device__ int g_count = 0;

__global__ __launch_bounds__(TPB, 1)
void hausdorff_kernel(const float* __restrict__ predict,
                      const float* __restrict__ target,
                      float* __restrict__ out)
{
    const int bx    = blockIdx.x;
    const int blk16 = bx & 15;        // (sample, dir)
    const int slice = bx >> 4;        // 1024-pixel slice this CTA owns
    const int s     = blk16 >> 1;
    const int dir   = blk16 & 1;
    const int tid   = threadIdx.x;

    __shared__ unsigned char tgm[HW];   // target mask
    __shared__ short gF[HW];            // forward column scan
    __shared__ short gB[HW];            // backward column scan
    __shared__ int   hsq[HW];           // min(gF,gB)^2 + jp^2
    __shared__ int   warpmax[32];
    __shared__ int   lastflag;

    const float* pbase = predict + s * HW;
    const float* tbase = target  + s * HW;
    const float* tsrc  = dir ? pbase : tbase;   // target-mask source array

    // ---- build target mask, vectorized (round-half-even like jnp.round) ----
    const float4* t4 = (const float4*)tsrc;
    #pragma unroll
    for (int v = 0; v < 3; ++v) {
        int idx = v * TPB + tid;
        if (idx < HW / 4) {
            float4 x = t4[idx];
            uchar4 m;
            m.x = rintf(x.x) > 0.5f;
            m.y = rintf(x.y) > 0.5f;
            m.z = rintf(x.z) > 0.5f;
            m.w = rintf(x.w) > 0.5f;
            ((uchar4*)tgm)[idx] = m;
        }
    }

    // ---- this thread's single source-pixel bit (register, no smem) ----
    const int q0 = slice * TPB + tid;
    const bool abit   = rintf(pbase[q0]) > 0.5f;
    const bool bbit   = rintf(tbase[q0]) > 0.5f;
    const bool srcbit = dir ? (bbit && !abit) : (abit && !bbit);
    __syncthreads();

    // ---- phase 1: per-column nearest-set-row scans (fwd/bwd in parallel) ----
    if (tid < DIM) {
        const int j = tid;
        int d = INFG;
        #pragma unroll
        for (int i = 0; i < DIM; ++i) {
            d = tgm[i * DIM + j] ? 0 : (d + 1);
            gF[i * DIM + j] = (short)d;
        }
    } else if (tid < 2 * DIM) {
        const int j = tid - DIM;
        int d = INFG;
        #pragma unroll
        for (int i = DIM - 1; i >= 0; --i) {
            d = tgm[i * DIM + j] ? 0 : (d + 1);
            gB[i * DIM + j] = (short)d;
        }
    }
    __syncthreads();

    // ---- combine: hsq[i][jp] = g^2 + jp^2  (enables 2-op hot loop) ----
    #pragma unroll
    for (int r = 0; r < HW / TPB; ++r) {
        int q  = r * TPB + tid;
        int i  = q / DIM;
        int jp = q - i * DIM;
        int g  = min((int)gF[q], (int)gB[q]);
        hsq[q] = g * g + jp * jp;
    }
    __syncthreads();

    // ---- phase 2: d^2 = min_jp (hsq[jp] - 2*j*jp) + j^2 ----
    const int i0 = q0 / DIM;
    const int j0 = q0 - i0 * DIM;
    const int* hrow = &hsq[i0 * DIM];   // 16B aligned (384B row stride)
    int m0 = 0x7fffffff, m1 = 0x7fffffff, m2 = 0x7fffffff, m3 = 0x7fffffff;
    #pragma unroll
    for (int jp = 0; jp < DIM; jp += 4) {
        int4 hh = *(const int4*)&hrow[jp];
        m0 = min(m0, hh.x - (2 * jp)     * j0);   // IMAD imm + IMNMX
        m1 = min(m1, hh.y - (2 * jp + 2) * j0);
        m2 = min(m2, hh.z - (2 * jp + 4) * j0);
        m3 = min(m3, hh.w - (2 * jp + 6) * j0);
    }
    int md2 = min(min(m0, m1), min(m2, m3)) + j0 * j0;
    int maxd2 = srcbit ? md2 : -1;

    // ---- block max-reduce (REDUX) ----
    int v = __reduce_max_sync(0xffffffffu, maxd2);
    if ((tid & 31) == 0) warpmax[tid >> 5] = v;
    __syncthreads();
    if (tid < 32) {
        int v2 = __reduce_max_sync(0xffffffffu, warpmax[tid]);
        if (tid == 0) {
            atomicMax(&g_max16[blk16], v2);
            __threadfence();
            int prev = atomicAdd(&g_count, 1);
            lastflag = (prev == NCTA - 1);
        }
    }
    __syncthreads();

    // ---- last CTA finalizes: max over dirs, mean over samples ----
    if (lastflag && tid < 32) {
        float dist = 0.0f;
        if (tid < NBLK16) {
            int vm = atomicExch(&g_max16[tid], -1);   // read + reset for next replay
            if (vm < 0)            dist = 0.0f;       // empty source set
            else if (vm > 1000000) dist = 1e9f;       // empty target set -> BIG
            else                   dist = sqrtf((float)vm) * (1.0f / (float)DIM);
        }
        float acc = 0.0f;
        #pragma unroll
        for (int ss = 0; ss < NSAMP; ++ss) {
            float d0 = __shfl_sync(0xffffffffu, dist, 2 * ss);
            float d1 = __shfl_sync(0xffffffffu, dist, 2 * ss + 1);
            acc += fmaxf(d0, d1);
        }
        if (tid == 0) {
            out[0]  = acc * (1.0f / (float)NSAMP);
            g_count = 0;   // reset for next graph replay
        }
    }
}

extern "C" void kernel_launch(void* const* d_in, const int* in_sizes, int n_in,
                              void* d_out, int out_size)
{
    const float* predict = (const float*)d_in[0];
    const float* target  = (const float*)d_in[1];
    float* out = (float*)d_out;

    hausdorff_kernel<<<NCTA, TPB>>>(predict, target, out);
}

// round 4
// speedup vs baseline: 1.5627x; 1.5627x over previous
#include <cuda_runtime.h>
#include <cuda_bf16.h>
#include <math.h>

#define HW     9216    // 96*96
#define DIM    96
#define NSAMP  8
#define NBLK16 16      // sample * direction
#define NSLICE 9
#define NCTA   (NBLK16 * NSLICE)   // 144 CTAs = single wave
#define TPB    1024
#define INFG   3000    // (INFG+96)^2 ~ 9.59e6 < 2^24 (fp32-exact)

__device__ int g_part[NCTA];
__device__ int g_count = 0;

__global__ __launch_bounds__(TPB, 1)
void hausdorff_kernel(const float* __restrict__ predict,
                      const float* __restrict__ target,
                      float* __restrict__ out)
{
    const int bx    = blockIdx.x;
    const int blk16 = bx & 15;
    const int slice = bx >> 4;
    const int s     = blk16 >> 1;
    const int dir   = blk16 & 1;
    const int tid   = threadIdx.x;
    const int lane  = tid & 31;

    __shared__ unsigned char tgm[HW];   // target mask
    __shared__ short gF[HW];            // forward column scan
    __shared__ short gB[HW];            // backward column scan
    __shared__ float hsqf[HW];          // float(min(gF,gB)^2 + jp^2)
    __shared__ int   warpmax[32];
    __shared__ int   lastflag;

    const float* pbase = predict + s * HW;
    const float* tbase = target  + s * HW;
    const float* tsrc  = dir ? pbase : tbase;

    // ---- build target mask, vectorized; mask = (x > 0.5f) == (rint(x) > 0.5) on [0,1) ----
    const float4* t4 = (const float4*)tsrc;
    #pragma unroll
    for (int v = 0; v < 3; ++v) {
        int idx = v * TPB + tid;
        if (idx < HW / 4) {
            float4 x = t4[idx];
            uchar4 m;
            m.x = x.x > 0.5f;
            m.y = x.y > 0.5f;
            m.z = x.z > 0.5f;
            m.w = x.w > 0.5f;
            ((uchar4*)tgm)[idx] = m;
        }
    }

    // ---- this thread's source-pixel bit (register, no smem) ----
    const int q0 = slice * TPB + tid;
    const bool abit   = pbase[q0] > 0.5f;
    const bool bbit   = tbase[q0] > 0.5f;
    const bool srcbit = dir ? (bbit && !abit) : (abit && !bbit);
    __syncthreads();

    // ---- phase 1: per-column nearest-set-row scans (fwd/bwd in parallel) ----
    if (tid < DIM) {
        const int j = tid;
        int d = INFG;
        #pragma unroll
        for (int i = 0; i < DIM; ++i) {
            d = tgm[i * DIM + j] ? 0 : (d + 1);
            gF[i * DIM + j] = (short)d;
        }
    } else if (tid < 2 * DIM) {
        const int j = tid - DIM;
        int d = INFG;
        #pragma unroll
        for (int i = DIM - 1; i >= 0; --i) {
            d = tgm[i * DIM + j] ? 0 : (d + 1);
            gB[i * DIM + j] = (short)d;
        }
    }
    __syncthreads();

    // ---- combine: hsqf[i][jp] = float(g^2 + jp^2); division-free indexing ----
    {
        const int ibase = (tid >> 5) * 3;   // warp id * 3 -> rows [ibase, ibase+3)
        #pragma unroll
        for (int di = 0; di < 3; ++di) {
            #pragma unroll
            for (int dj = 0; dj < 3; ++dj) {
                int i  = ibase + di;
                int jp = lane + 32 * dj;
                int q  = i * DIM + jp;
                int g  = min((int)gF[q], (int)gB[q]);
                hsqf[q] = (float)(g * g + jp * jp);
            }
        }
    }
    __syncthreads();

    // ---- phase 2: d^2 = min_jp (h[jp] - 2*jp*j0) + j0^2 (fp32-exact) ----
    const int i0 = q0 / DIM;
    const int j0 = q0 - i0 * DIM;
    float mres = -1.0f;                 // sentinel: not a source pixel
    if (srcbit) {
        const float j0f = (float)j0;
        const float* hrow = &hsqf[i0 * DIM];   // warp-uniform -> broadcast LDS
        float m0 = 3.0e7f, m1 = 3.0e7f, m2 = 3.0e7f, m3 = 3.0e7f;
        #pragma unroll
        for (int jp = 0; jp < DIM; jp += 4) {
            float4 hh = *(const float4*)&hrow[jp];
            m0 = fminf(m0, fmaf(j0f, (float)(-2 * jp),     hh.x));  // FFMA-imm
            m1 = fminf(m1, fmaf(j0f, (float)(-2 * jp - 2), hh.y));
            m2 = fminf(m2, fmaf(j0f, (float)(-2 * jp - 4), hh.z));
            m3 = fminf(m3, fmaf(j0f, (float)(-2 * jp - 6), hh.w));
        }
        mres = fminf(fminf(m0, m1), fminf(m2, m3)) + (float)(j0 * j0);
    }

    // ---- block max-reduce on float bits (order-preserving for our values) ----
    int v = __reduce_max_sync(0xffffffffu, __float_as_int(mres));
    if (lane == 0) warpmax[tid >> 5] = v;
    __syncthreads();
    if (tid < 32) {
        int v2 = __reduce_max_sync(0xffffffffu, warpmax[tid]);
        if (tid == 0) {
            g_part[bx] = v2;
            __threadfence();
            int prev = atomicAdd(&g_count, 1);
            lastflag = (prev == NCTA - 1);
        }
    }
    __syncthreads();

    // ---- last CTA finalizes ----
    if (lastflag && tid < 32) {
        float dist = 0.0f;
        if (tid < NBLK16) {
            int vm = 0x80000000;
            #pragma unroll
            for (int k = 0; k < NSLICE; ++k)
                vm = max(vm, __ldcg(&g_part[k * NBLK16 + tid]));
            float d2 = __int_as_float(vm);
            if (d2 < 0.0f)          dist = 0.0f;   // empty source set
            else if (d2 > 1.0e6f)   dist = 1e9f;   // empty target set -> BIG
            else                    dist = sqrtf(d2) * (1.0f / (float)DIM);
        }
        float acc = 0.0f;
        #pragma unroll
        for (int ss = 0; ss < NSAMP; ++ss) {
            float d0 = __shfl_sync(0xffffffffu, dist, 2 * ss);
            float d1 = __shfl_sync(0xffffffffu, dist, 2 * ss + 1);
            acc += fmaxf(d0, d1);
        }
        if (tid == 0) {
            out[0]  = acc * (1.0f / (float)NSAMP);
            g_count = 0;   // reset for next graph replay
        }
    }
}

extern "C" void kernel_launch(void* const* d_in, const int* in_sizes, int n_in,
                              void* d_out, int out_size)
{
    const float* predict = (const float*)d_in[0];
    const float* target  = (const float*)d_in[1];
    float* out = (float*)d_out;

    hausdorff_kernel<<<NCTA, TPB>>>(predict, target, out);
}

// round 6
// speedup vs baseline: 1.5811x; 1.0118x over previous
#include <cuda_runtime.h>
#include <cuda_bf16.h>
#include <math.h>

#define HW     9216    // 96*96
#define DIM    96
#define NSAMP  8
#define NBLK16 16
#define NSLICE 9
#define NCTA   (NBLK16 * NSLICE)   // 144 CTAs = single wave
#define TPB    1024
#define INFG   3000    // (INFG+96)^2 ~ 9.6e6 < 2^24 (fp32-exact)
#define NRWIN  12      // 1024 pixels span <= 12 rows

__device__ int g_part[NCTA];
__device__ int g_count = 0;

__global__ __launch_bounds__(TPB, 1)
void hausdorff_kernel(const float* __restrict__ predict,
                      const float* __restrict__ target,
                      float* __restrict__ out)
{
    const int bx    = blockIdx.x;
    const int blk16 = bx & 15;
    const int slice = bx >> 4;
    const int s     = blk16 >> 1;
    const int dir   = blk16 & 1;
    const int tid   = threadIdx.x;
    const int lane  = tid & 31;

    __shared__ unsigned char tgm[HW];                 // target mask
    __shared__ short gFs[NRWIN * DIM];                // fwd scan, window
    __shared__ short gBs[NRWIN * DIM];                // bwd scan, window
    __shared__ __align__(16) float hsqf[NRWIN * DIM]; // g^2 + jp^2 (window)
    __shared__ int   warpmax[32];
    __shared__ int   lastflag;

    const int r0 = (slice * TPB) / DIM;               // first row this CTA needs

    const float* pbase = predict + s * HW;
    const float* tbase = target  + s * HW;
    const float* tsrc  = dir ? pbase : tbase;

    // ---- build target mask, vectorized ((x > 0.5f) == (rint(x) > 0.5) on [0,1)) ----
    const float4* t4 = (const float4*)tsrc;
    #pragma unroll
    for (int v = 0; v < 3; ++v) {
        int idx = v * TPB + tid;
        if (idx < HW / 4) {
            float4 x = t4[idx];
            uchar4 m;
            m.x = x.x > 0.5f;
            m.y = x.y > 0.5f;
            m.z = x.z > 0.5f;
            m.w = x.w > 0.5f;
            ((uchar4*)tgm)[idx] = m;
        }
    }

    // ---- this thread's source-pixel bit (register, no smem) ----
    const int q0 = slice * TPB + tid;
    const bool abit   = pbase[q0] > 0.5f;
    const bool bbit   = tbase[q0] > 0.5f;
    const bool srcbit = dir ? (bbit && !abit) : (abit && !bbit);
    __syncthreads();

    // ---- phase 1: full-column scans, store ONLY the window rows ----
    if (tid < DIM) {
        const int j = tid;
        int d = INFG;
        #pragma unroll
        for (int i = 0; i < DIM; ++i) {
            d = tgm[i * DIM + j] ? 0 : (d + 1);
            if ((unsigned)(i - r0) < NRWIN)
                gFs[(i - r0) * DIM + j] = (short)d;
        }
    } else if (tid < 2 * DIM) {
        const int j = tid - DIM;
        int d = INFG;
        #pragma unroll
        for (int i = DIM - 1; i >= 0; --i) {
            d = tgm[i * DIM + j] ? 0 : (d + 1);
            if ((unsigned)(i - r0) < NRWIN)
                gBs[(i - r0) * DIM + j] = (short)d;
        }
    }
    __syncthreads();

    // ---- mini-combine over the window: hsqf = float(g^2 + jp^2) ----
    {
        int e = tid;
        if (e < NRWIN * DIM) {
            int iloc = e / DIM;
            int jp   = e - iloc * DIM;
            int g    = min((int)gFs[e], (int)gBs[e]);
            hsqf[e]  = (float)(g * g + jp * jp);
        }
        e = TPB + tid;
        if (e < NRWIN * DIM) {
            int iloc = e / DIM;
            int jp   = e - iloc * DIM;
            int g    = min((int)gFs[e], (int)gBs[e]);
            hsqf[e]  = (float)(g * g + jp * jp);
        }
    }
    __syncthreads();

    // ---- phase 2: d^2 = min_jp (h[jp] - 2*jp*j0) + j0^2 (fp32-exact) ----
    const int i0   = q0 / DIM;
    const int j0   = q0 - i0 * DIM;
    const int iloc = i0 - r0;
    float mres = -1.0f;                 // sentinel: not a source pixel
    if (srcbit) {
        const float j0f = (float)j0;
        const float* hrow = &hsqf[iloc * DIM];   // warp-uniform -> broadcast LDS
        float m0 = 3.0e7f, m1 = 3.0e7f, m2 = 3.0e7f, m3 = 3.0e7f;
        #pragma unroll
        for (int jp = 0; jp < DIM; jp += 4) {
            float4 hh = *(const float4*)&hrow[jp];
            m0 = fminf(m0, fmaf(j0f, (float)(-2 * jp),     hh.x));  // FFMA-imm
            m1 = fminf(m1, fmaf(j0f, (float)(-2 * jp - 2), hh.y));
            m2 = fminf(m2, fmaf(j0f, (float)(-2 * jp - 4), hh.z));
            m3 = fminf(m3, fmaf(j0f, (float)(-2 * jp - 6), hh.w));
        }
        mres = fminf(fminf(m0, m1), fminf(m2, m3)) + (float)(j0 * j0);
    }

    // ---- block max-reduce on float bits (order-preserving for our values) ----
    int v = __reduce_max_sync(0xffffffffu, __float_as_int(mres));
    if (lane == 0) warpmax[tid >> 5] = v;
    __syncthreads();
    if (tid < 32) {
        int v2 = __reduce_max_sync(0xffffffffu, warpmax[tid]);
        if (tid == 0) {
            g_part[bx] = v2;
            __threadfence();
            int prev = atomicAdd(&g_count, 1);
            lastflag = (prev == NCTA - 1);
        }
    }
    __syncthreads();

    // ---- last CTA finalizes ----
    if (lastflag && tid < 32) {
        float dist = 0.0f;
        if (tid < NBLK16) {
            int vm = 0x80000000;
            #pragma unroll
            for (int k = 0; k < NSLICE; ++k)
                vm = max(vm, __ldcg(&g_part[k * NBLK16 + tid]));
            float d2 = __int_as_float(vm);
            if (d2 < 0.0f)          dist = 0.0f;   // empty source set
            else if (d2 > 1.0e6f)   dist = 1e9f;   // empty target set -> BIG
            else                    dist = sqrtf(d2) * (1.0f / (float)DIM);
        }
        float acc = 0.0f;
        #pragma unroll
        for (int ss = 0; ss < NSAMP; ++ss) {
            float d0 = __shfl_sync(0xffffffffu, dist, 2 * ss);
            float d1 = __shfl_sync(0xffffffffu, dist, 2 * ss + 1);
            acc += fmaxf(d0, d1);
        }
        if (tid == 0) {
            out[0]  = acc * (1.0f / (float)NSAMP);
            g_count = 0;   // reset for next graph replay
        }
    }
}

extern "C" void kernel_launch(void* const* d_in, const int* in_sizes, int n_in,
                              void* d_out, int out_size)
{
    const float* predict = (const float*)d_in[0];
    const float* target  = (const float*)d_in[1];
    float* out = (float*)d_out;

    hausdorff_kernel<<<NCTA, TPB>>>(predict, target, out);
}